// round 16
// baseline (speedup 1.0000x reference)
#include <cuda_runtime.h>
#include <cuda_fp16.h>
#include <stdint.h>

#define T_STEPS 15
#define C_IN    6
#define HW      256
#define NPIX    65536
#define C_OUT   64
#define THRESH  15.0f
#define NELEM   62914560
#define QTOT    160              // 150 real taps + 10 zero pads, q=(ky*5+kx)*6+i
#define NKB     64               // kwta blocks
#define BSTRIDE 44               // smem column stride in uint4 (bank-conflict-free)

__device__ __align__(16) uint4   g_wB[64 * 40];      // packed B frags [c][ch][b]
__device__ __align__(16) float   g_wqc[QTOT * 64];   // exact fp32 [q][c]
__device__ __align__(16) uint4   g_ftq[10 * NPIX];   // tf bytes, q-ordered
__device__ int                   g_winfo[NPIX];      // -1 or wc|(count<<8)
__device__ unsigned char         g_wc[NPIX];         // 255 none, 254 flagged
__device__ float                 g_firstpot[NPIX];
__device__ float                 g_winval[NPIX * 16];
__device__ float                 g_gband;
__device__ int                   g_vmax;
__device__ int                   g_nflag;
__device__ int                   g_flag[NPIX];
__device__ unsigned long long    g_part[NKB];
__device__ int                   g_banc[5];
__device__ int                   g_banp[5];
__device__ volatile int          g_barcnt;

// weight in q-order (q = (ky*5+kx)*6 + i); 0 for pad taps
__device__ __forceinline__ float wq(const float* wg, int c, int q)
{
    if (q >= 150) return 0.f;
    const int i = q % 6, r = q / 6, kx = r % 5, ky = r / 5;
    return wg[c * 150 + i * 25 + ky * 5 + kx];
}
__device__ __forceinline__ unsigned packh(float a, float b)
{
    const __half2 h = __halves2half2(__float2half_rn(a), __float2half_rn(b));
    return *(const unsigned*)&h;
}

// ---------------- K0: fused weight prep (blocks 0..51) + ftq (52..307) ------
__global__ __launch_bounds__(256) void prep_ftq_kernel(const float* __restrict__ in,
                                                       const float* __restrict__ wg)
{
    __shared__ unsigned char sft[C_IN * 20 * 20];
    const int tid = threadIdx.x;

    if (blockIdx.x < 52) {
        if (blockIdx.x == 51) {                  // control block
            __shared__ float sb[64];
            if (tid == 0) { g_nflag = 0; g_vmax = 0; *(int*)&g_barcnt = 0; }
            if (tid < 64) {
                float s = 0.f;
                for (int j = 0; j < 150; j++) {
                    const float w = wg[tid * 150 + j];
                    const float h1 = __half2float(__float2half_rn(w));
                    const float h2 = __half2float(__float2half_rn(w - h1));
                    s += fabsf(w - h1 - h2);     // exact residual magnitude
                }
                sb[tid] = s;
            }
            __syncthreads();
            if (tid < 32) sb[tid] = fmaxf(sb[tid], sb[tid + 32]);
            __syncwarp();
            if (tid < 16) sb[tid] = fmaxf(sb[tid], sb[tid + 16]);
            __syncwarp();
            if (tid < 8)  sb[tid] = fmaxf(sb[tid], sb[tid + 8]);
            __syncwarp();
            if (tid < 4)  sb[tid] = fmaxf(sb[tid], sb[tid + 4]);
            __syncwarp();
            // ref-chain drift 1.3e-3 + fused-accumulator rounding + key-mask + slack
            if (tid == 0) g_gband = fmaxf(fmaxf(sb[0], sb[1]), fmaxf(sb[2], sb[3])) + 1.7e-3f;
            return;
        }
        const int k = blockIdx.x * 256 + tid;
        if (k < 2560) {                          // packed B fragment records
            const int c = k / 40, r = k % 40, ch = r / 4, b = r % 4;
            const int q0 = ch * 16 + b * 2;
            float w0 = wq(wg, c, q0),     w1 = wq(wg, c, q0 + 1);
            float w8 = wq(wg, c, q0 + 8), w9 = wq(wg, c, q0 + 9);
            const float a0 = __half2float(__float2half_rn(w0));
            const float a1 = __half2float(__float2half_rn(w1));
            const float a8 = __half2float(__float2half_rn(w8));
            const float a9 = __half2float(__float2half_rn(w9));
            uint4 W;
            W.x = packh(w0, w1);                 // h1 @ k0,k0+1
            W.y = packh(w8, w9);                 // h1 @ k0+8,k0+9
            W.z = packh(w0 - a0, w1 - a1);       // h2 @ k0,k0+1
            W.w = packh(w8 - a8, w9 - a9);       // h2 @ k0+8,k0+9
            g_wB[k] = W;
        } else if (k < 2560 + QTOT * 64) {       // exact fp32 [q][c]
            const int idx = k - 2560;
            const int q = idx >> 6, c = idx & 63;
            g_wqc[q * 64 + c] = wq(wg, c, q);
        }
        return;
    }

    // ---- ftq part: fused first-spike-time + q-ordered byte stream ----
    const int fb = blockIdx.x - 52;              // 0..255
    const int x0 = (fb & 15) * 16, y0 = (fb >> 4) * 16;
    for (int k = tid; k < C_IN * 400; k += 256) {
        const int i = k / 400, rr = k % 400, yy = rr / 20, xx = rr % 20;
        const int gy = y0 + yy - 2, gx = x0 + xx - 2;
        unsigned char tf = 15;
        if (gy >= 0 && gy < HW && gx >= 0 && gx < HW) {
            const size_t base = (size_t)i * NPIX + gy * HW + gx;
#pragma unroll
            for (int t = T_STEPS - 1; t >= 0; t--)
                if (in[(size_t)t * C_IN * NPIX + base] > 0.f) tf = (unsigned char)t;
        }
        sft[k] = tf;
    }
    __syncthreads();
    const int px = tid & 15, py = tid >> 4;
    const int pix = (y0 + py) * HW + x0 + px;
#pragma unroll
    for (int ch = 0; ch < 10; ch++) {
        unsigned r[4] = {0u, 0u, 0u, 0u};
#pragma unroll
        for (int b = 0; b < 16; b++) {
            const int q = ch * 16 + b;
            unsigned v = 15u;
            if (q < 150) {
                const int ky = q / 30, kx = (q / 6) % 5, i = q % 6;
                v = sft[(i * 20 + py + ky) * 20 + px + kx];
            }
            r[b >> 2] |= v << ((b & 3) * 8);
        }
        g_ftq[ch * NPIX + pix] = make_uint4(r[0], r[1], r[2], r[3]);
    }
}

#define MMAH(d0,d1,d2,d3,a0,a1,a2,a3,b0,b1) \
    asm("mma.sync.aligned.m16n8k16.row.col.f32.f16.f16.f32 " \
        "{%0,%1,%2,%3},{%4,%5,%6,%7},{%8,%9},{%0,%1,%2,%3};" \
        : "+f"(d0),"+f"(d1),"+f"(d2),"+f"(d3) \
        : "r"(a0),"r"(a1),"r"(a2),"r"(a3),"r"(b0),"r"(b1))

// float top-2 (keys are non-negative): 3 FMNMX, fma-pipe eligible
#define TUPDF(m1,m2,kf) { (m2) = fmaxf((m2), fminf((m1), (kf))); (m1) = fmaxf((m1), (kf)); }

// per-pixel epilogue (identical decision bits to R11..R15)
__device__ __forceinline__ void mma_epilogue(
    int pix, int warp, int lane, int kq, int t1, float gb,
    float m1a, float m2a, float m1b, float m2b,
    unsigned (*su1)[16], unsigned (*su2)[16])
{
#pragma unroll
    for (int off = 1; off <= 2; off <<= 1) {
        float o1 = __shfl_xor_sync(0xffffffffu, m1a, off);
        float o2 = __shfl_xor_sync(0xffffffffu, m2a, off);
        m2a = fmaxf(m2a, o2); m2a = fmaxf(m2a, fminf(m1a, o1)); m1a = fmaxf(m1a, o1);
        o1 = __shfl_xor_sync(0xffffffffu, m1b, off);
        o2 = __shfl_xor_sync(0xffffffffu, m2b, off);
        m2b = fmaxf(m2b, o2); m2b = fmaxf(m2b, fminf(m1b, o1)); m1b = fmaxf(m1b, o1);
    }
    if (kq == 0) {
        su1[warp][t1] = __float_as_uint(m1a); su2[warp][t1] = __float_as_uint(m2a);
        if (t1 + 8 < 15) { su1[warp][t1 + 8] = __float_as_uint(m1b); su2[warp][t1 + 8] = __float_as_uint(m2b); }
    }
    __syncwarp();
    if (lane == 0) {
        bool flag = false;
        int te = 15;
#pragma unroll
        for (int t = 0; t < 15; t++) {
            const float m = __uint_as_float(su1[warp][t] & 0xFFFFFFC0u);
            if (fabsf(m - THRESH) < gb) flag = true;
            if (te == 15 && m >= THRESH) te = t;
        }
        if (te < 15) {
            const float v1 = __uint_as_float(su1[warp][te] & 0xFFFFFFC0u);
            const float v2 = __uint_as_float(su2[warp][te] & 0xFFFFFFC0u);
            if (v1 - v2 < 2.f * gb) flag = true;
        }
        if (flag) {
            const int s = atomicAdd(&g_nflag, 1);
            g_flag[s] = pix;
            g_wc[pix] = 254;
        } else if (te < 15) {
            const int cw = 63 - (int)(su1[warp][te] & 63u);
            g_wc[pix]    = (unsigned char)cw;
            g_winfo[pix] = cw | ((15 - te) << 8);
        } else {
            g_wc[pix] = 255; g_winfo[pix] = -1; g_firstpot[pix] = 0.f;
        }
    }
    __syncwarp();
}

// ---------------- K1: MMA decision conv (pixel-pair B reuse, ch-outer) ------
__global__ __launch_bounds__(256, 3) void mma_kernel()
{
    __shared__ __align__(16) uint4 swB[64 * BSTRIDE];   // 45056 B
    __shared__ unsigned su1[8][16], su2[8][16];

    const int tid = threadIdx.x;
    for (int k = tid; k < 2560; k += 256) {
        const int c = k / 40, r = k % 40;
        swB[c * BSTRIDE + r] = g_wB[k];
    }
    __syncthreads();

    const int lane = tid & 31, warp = tid >> 5;
    const int t1 = lane >> 2;
    const int k0 = (lane & 3) * 2;
    const int kq = lane & 3;
    const int nB = lane >> 2;
    const unsigned tt1 = (unsigned)t1 * 0x01010101u;
    const unsigned tt2 = (unsigned)(t1 + 8) * 0x01010101u;
    const unsigned sel = ((k0 & 3) == 0) ? 0x1404u : 0x3424u;
    const float gb = g_gband;

    for (int pp = 0; pp < 4; pp++) {
        const int pix0 = blockIdx.x * 64 + warp * 8 + pp * 2;
        const int pix1 = pix0 + 1;

        float acc0[8][4], acc1[8][4];
#pragma unroll
        for (int nt = 0; nt < 8; nt++)
#pragma unroll
            for (int j = 0; j < 4; j++) { acc0[nt][j] = 0.f; acc1[nt][j] = 0.f; }

#pragma unroll
        for (int ch = 0; ch < 10; ch++) {
            const uint4 T0 = __ldg(&g_ftq[ch * NPIX + pix0]);
            const uint4 T1 = __ldg(&g_ftq[ch * NPIX + pix1]);
            const unsigned wa0 = (k0 < 4) ? T0.x : T0.y;
            const unsigned wb0 = (k0 < 4) ? T0.z : T0.w;
            const unsigned wa1 = (k0 < 4) ? T1.x : T1.y;
            const unsigned wb1 = (k0 < 4) ? T1.z : T1.w;
            const unsigned A00 = __byte_perm(__vcmpleu4(wa0, tt1), 0, sel) & 0x3C003C00u;
            const unsigned A01 = __byte_perm(__vcmpleu4(wa0, tt2), 0, sel) & 0x3C003C00u;
            const unsigned A02 = __byte_perm(__vcmpleu4(wb0, tt1), 0, sel) & 0x3C003C00u;
            const unsigned A03 = __byte_perm(__vcmpleu4(wb0, tt2), 0, sel) & 0x3C003C00u;
            const unsigned A10 = __byte_perm(__vcmpleu4(wa1, tt1), 0, sel) & 0x3C003C00u;
            const unsigned A11 = __byte_perm(__vcmpleu4(wa1, tt2), 0, sel) & 0x3C003C00u;
            const unsigned A12 = __byte_perm(__vcmpleu4(wb1, tt1), 0, sel) & 0x3C003C00u;
            const unsigned A13 = __byte_perm(__vcmpleu4(wb1, tt2), 0, sel) & 0x3C003C00u;
#pragma unroll
            for (int nt = 0; nt < 8; nt++) {
                const uint4 W = swB[(nt * 8 + nB) * BSTRIDE + ch * 4 + kq];
                MMAH(acc0[nt][0], acc0[nt][1], acc0[nt][2], acc0[nt][3], A00, A01, A02, A03, W.x, W.y);
                MMAH(acc0[nt][0], acc0[nt][1], acc0[nt][2], acc0[nt][3], A00, A01, A02, A03, W.z, W.w);
                MMAH(acc1[nt][0], acc1[nt][1], acc1[nt][2], acc1[nt][3], A10, A11, A12, A13, W.x, W.y);
                MMAH(acc1[nt][0], acc1[nt][1], acc1[nt][2], acc1[nt][3], A10, A11, A12, A13, W.z, W.w);
            }
        }

        float m1a0 = 0.f, m2a0 = 0.f, m1b0 = 0.f, m2b0 = 0.f;
        float m1a1 = 0.f, m2a1 = 0.f, m1b1 = 0.f, m2b1 = 0.f;
#pragma unroll
        for (int nt = 0; nt < 8; nt++) {
            const unsigned c0 = (unsigned)(nt * 8 + kq * 2);
            float k00 = __uint_as_float((__float_as_uint(acc0[nt][0]) & 0xFFFFFFC0u) | (63u - c0));
            float k01 = __uint_as_float((__float_as_uint(acc0[nt][1]) & 0xFFFFFFC0u) | (62u - c0));
            float k02 = __uint_as_float((__float_as_uint(acc0[nt][2]) & 0xFFFFFFC0u) | (63u - c0));
            float k03 = __uint_as_float((__float_as_uint(acc0[nt][3]) & 0xFFFFFFC0u) | (62u - c0));
            TUPDF(m1a0, m2a0, k00); TUPDF(m1a0, m2a0, k01);
            TUPDF(m1b0, m2b0, k02); TUPDF(m1b0, m2b0, k03);
            k00 = __uint_as_float((__float_as_uint(acc1[nt][0]) & 0xFFFFFFC0u) | (63u - c0));
            k01 = __uint_as_float((__float_as_uint(acc1[nt][1]) & 0xFFFFFFC0u) | (62u - c0));
            k02 = __uint_as_float((__float_as_uint(acc1[nt][2]) & 0xFFFFFFC0u) | (63u - c0));
            k03 = __uint_as_float((__float_as_uint(acc1[nt][3]) & 0xFFFFFFC0u) | (62u - c0));
            TUPDF(m1a1, m2a1, k00); TUPDF(m1a1, m2a1, k01);
            TUPDF(m1b1, m2b1, k02); TUPDF(m1b1, m2b1, k03);
        }

        mma_epilogue(pix0, warp, lane, kq, t1, gb, m1a0, m2a0, m1b0, m2b0, su1, su2);
        mma_epilogue(pix1, warp, lane, kq, t1, gb, m1a1, m2a1, m1b1, m2b1, su1, su2);
    }
}

// ---------------- K2: fused series (blocks 0..1023, 4 thr/pixel) + fallback -
__global__ __launch_bounds__(256) void series_fb_kernel()
{
    __shared__ float swq[QTOT * 64];
    const int tid = threadIdx.x;
    const int lane = tid & 31, warp = tid >> 5;

    if (blockIdx.x < 1024) {
        // ---- exact winner series, 4 threads per pixel (t-quarter split) ----
        for (int k = tid; k < QTOT * 64; k += 256) swq[k] = g_wqc[k];
        __syncthreads();

        const int u = blockIdx.x * 256 + tid;   // 4*NPIX units
        const int pix = u >> 2, quarter = u & 3;
        const int wc = g_wc[pix];
        if (wc >= 64) return;
        const int t0 = quarter * 4;             // t range [t0, t0+4) (t=15 dropped)

        float acc[4];
#pragma unroll
        for (int j = 0; j < 4; j++) acc[j] = 0.f;

#pragma unroll
        for (int ch = 0; ch < 10; ch++) {
            const uint4 T = __ldg(&g_ftq[ch * NPIX + pix]);
            const unsigned W[4] = {T.x, T.y, T.z, T.w};
#pragma unroll
            for (int b = 0; b < 16; b++) {
                const int tf = (W[b >> 2] >> ((b & 3) * 8)) & 255;
                const float w = swq[(ch * 16 + b) * 64 + wc];
#pragma unroll
                for (int j = 0; j < 4; j++)
                    if (tf <= t0 + j) acc[j] += w;   // exact skip-zero chain, q order
            }
        }
        const int te = 15 - (g_winfo[pix] >> 8);
#pragma unroll
        for (int j = 0; j < 4; j++) {
            const int t = t0 + j;
            if (t < 15) {
                const float v = (acc[j] >= THRESH) ? acc[j] : 0.f;
                g_winval[pix * 16 + t] = v;
                if (t == te) {
                    g_firstpot[pix] = v;
                    atomicMax(&g_vmax, __float_as_int(v));
                }
            }
        }
        return;
    }

    // ---- exact fallback, warp per flagged pixel (2 channels per lane) ----
    const int gw = (blockIdx.x - 1024) * 8 + warp;    // 0..4095
    const int nf = g_nflag;
    for (int f = gw; f < nf; f += 4096) {
        const int pix = g_flag[f];
        float acc0[15], acc1[15];
#pragma unroll
        for (int t = 0; t < 15; t++) { acc0[t] = 0.f; acc1[t] = 0.f; }
#pragma unroll
        for (int ch = 0; ch < 10; ch++) {
            const uint4 T = __ldg(&g_ftq[ch * NPIX + pix]);
            const unsigned W[4] = {T.x, T.y, T.z, T.w};
#pragma unroll
            for (int b = 0; b < 16; b++) {
                const int tf = (W[b >> 2] >> ((b & 3) * 8)) & 255;
                const float w0 = g_wqc[(ch * 16 + b) * 64 + lane];
                const float w1 = g_wqc[(ch * 16 + b) * 64 + lane + 32];
#pragma unroll
                for (int t = 0; t < 15; t++)
                    if (tf <= t) { acc0[t] += w0; acc1[t] += w1; }
            }
        }
        int te = 15;
        unsigned long long kte = 0ull;
#pragma unroll
        for (int t = 0; t < 15; t++) {
            const float v0 = (acc0[t] >= THRESH) ? acc0[t] : 0.f;
            const float v1 = (acc1[t] >= THRESH) ? acc1[t] : 0.f;
            unsigned long long k0 = ((unsigned long long)__float_as_uint(v0) << 8) | (unsigned)(63 - lane);
            unsigned long long k1 = ((unsigned long long)__float_as_uint(v1) << 8) | (unsigned)(31 - lane);
            unsigned long long k = (k0 > k1) ? k0 : k1;
#pragma unroll
            for (int off = 16; off; off >>= 1) {
                const unsigned long long o = __shfl_xor_sync(0xffffffffu, k, off);
                if (o > k) k = o;
            }
            if (te == 15 && (k >> 8) != 0ull) { te = t; kte = k; }
        }
        int cw = -1;
        if (te < 15) cw = 63 - (int)(kte & 0xff);
        if (lane == 0) {
            if (te < 15) {
                const float fp = __uint_as_float((unsigned)(kte >> 8));
                g_wc[pix] = (unsigned char)cw;
                g_winfo[pix] = cw | ((15 - te) << 8);
                g_firstpot[pix] = fp;
                atomicMax(&g_vmax, __float_as_int(fp));
            } else {
                g_wc[pix] = 255; g_winfo[pix] = -1; g_firstpot[pix] = 0.f;
            }
        }
        if (cw >= 0) {
            const int owner = cw & 31, half = cw >> 5;
            if (lane == owner) {
#pragma unroll
                for (int t = 0; t < 15; t++) {
                    const float a = half ? acc1[t] : acc0[t];
                    g_winval[pix * 16 + t] = (a >= THRESH) ? a : 0.f;
                }
            }
        }
        __syncwarp();
    }
}

// ---------------- K3: fused kwta (blocks 0..63) + emit (64..61503) ----------
__device__ __forceinline__ void grid_bar(int target)
{
    __syncthreads();
    if (threadIdx.x == 0) {
        __threadfence();
        atomicAdd((int*)&g_barcnt, 1);
        while (g_barcnt < target * NKB) { }
    }
    __syncthreads();
}

__global__ __launch_bounds__(256) void emit_kwta_kernel(float* __restrict__ spk,
                                                        float* __restrict__ pot,
                                                        float* __restrict__ owin)
{
    if (blockIdx.x < NKB) {
        // ---- k-WTA: 5 greedy rounds with software grid barrier ----
        __shared__ unsigned long long sk[256];
        const int tid = threadIdx.x, bid = blockIdx.x;
        const float v = __int_as_float(g_vmax) * (float)T_STEPS;
        volatile int* vbanc = g_banc;
        volatile int* vbanp = g_banp;

        for (int round = 0; round < 5; round++) {
            int bc[4], bh[4], bw[4];
#pragma unroll
            for (int b = 0; b < 4; b++) {
                if (b < round) { bc[b] = vbanc[b]; const int bp = vbanp[b]; bh[b] = bp >> 8; bw[b] = bp & 255; }
                else           { bc[b] = -1; bh[b] = -1000; bw[b] = -1000; }
            }
            unsigned long long best = 0;
            for (int p = bid * 256 + tid; p < NPIX; p += NKB * 256) {
                const int info = g_winfo[p];
                if (info < 0) continue;
                const int wc = info & 255;
                const int h = p >> 8, w = p & 255;
                bool ban = false;
#pragma unroll
                for (int b = 0; b < 4; b++) {
                    if (wc == bc[b]) ban = true;
                    if (h >= bh[b] - 3 && h <= bh[b] + 3 && w >= bw[b] - 3 && w <= bw[b] + 3) ban = true;
                }
                if (ban) continue;
                const float tot = (float)(info >> 8) * (g_firstpot[p] + v);
                const unsigned flat = ((unsigned)wc << 16) | (unsigned)p;
                const unsigned long long key =
                    ((unsigned long long)__float_as_uint(tot) << 32) | (unsigned)(~flat);
                if (key > best) best = key;
            }
            sk[tid] = best;
            __syncthreads();
            for (int s = 128; s >= 1; s >>= 1) {
                if (tid < s && sk[tid + s] > sk[tid]) sk[tid] = sk[tid + s];
                __syncthreads();
            }
            if (tid == 0)
                *(volatile unsigned long long*)&g_part[bid] = sk[0];

            grid_bar(2 * round + 1);

            if (bid == 0) {
                if (tid < NKB) sk[tid] = *(volatile unsigned long long*)&g_part[tid];
                else           sk[tid] = 0;
                __syncthreads();
                for (int s = 32; s >= 1; s >>= 1) {
                    if (tid < s && sk[tid + s] > sk[tid]) sk[tid] = sk[tid + s];
                    __syncthreads();
                }
                if (tid == 0) {
                    const unsigned long long k = sk[0];
                    if ((k >> 32) != 0ull) {
                        const unsigned flat = ~(unsigned)(k & 0xffffffffull);
                        const int c = (int)(flat >> 16), p = (int)(flat & 0xffff);
                        owin[round * 3 + 0] = (float)c;
                        owin[round * 3 + 1] = (float)(p >> 8);
                        owin[round * 3 + 2] = (float)(p & 255);
                        g_banc[round] = c; g_banp[round] = p;
                    } else {
                        owin[round * 3 + 0] = -1.f; owin[round * 3 + 1] = -1.f; owin[round * 3 + 2] = -1.f;
                        g_banc[round] = -1; g_banp[round] = (1000 << 8);
                    }
                    __threadfence();
                }
            }
            grid_bar(2 * round + 2);
        }
        return;
    }

    // ---- emit spk/pot ----
    const size_t u = (size_t)(blockIdx.x - NKB) * 256 + threadIdx.x;
    const int w4 = (int)(u & 63);
    size_t r = u >> 6;
    const int h = (int)(r & 255); r >>= 8;
    const int c = (int)(r & 63);
    const int t = (int)(r >> 6);
    const int pix = (h << 8) | (w4 << 2);
    const uchar4 wc = *reinterpret_cast<const uchar4*>(g_wc + pix);
    const size_t e = ((size_t)t * C_OUT + (size_t)c) * NPIX + (size_t)pix;
    float4 pv, sv;
    float v;
    v = (wc.x == c) ? g_winval[(size_t)(pix + 0) * 16 + t] : 0.f; pv.x = v; sv.x = (v > 0.f) ? 1.f : 0.f;
    v = (wc.y == c) ? g_winval[(size_t)(pix + 1) * 16 + t] : 0.f; pv.y = v; sv.y = (v > 0.f) ? 1.f : 0.f;
    v = (wc.z == c) ? g_winval[(size_t)(pix + 2) * 16 + t] : 0.f; pv.z = v; sv.z = (v > 0.f) ? 1.f : 0.f;
    v = (wc.w == c) ? g_winval[(size_t)(pix + 3) * 16 + t] : 0.f; pv.w = v; sv.w = (v > 0.f) ? 1.f : 0.f;
    *reinterpret_cast<float4*>(pot + e) = pv;
    *reinterpret_cast<float4*>(spk + e) = sv;
}

// ---------------------------------------------------------------------------
extern "C" void kernel_launch(void* const* d_in, const int* in_sizes, int n_in,
                              void* d_out, int out_size)
{
    (void)in_sizes; (void)n_in; (void)out_size;
    const float* in = (const float*)d_in[0];
    const float* w1 = (const float*)d_in[1];
    float* out = (float*)d_out;
    float* spk = out;
    float* pot = out + (size_t)NELEM;
    float* win = out + (size_t)2 * NELEM;

    prep_ftq_kernel<<<308, 256>>>(in, w1);
    mma_kernel<<<1024, 256>>>();
    series_fb_kernel<<<1536, 256>>>();
    emit_kwta_kernel<<<NKB + NELEM / 4 / 256, 256>>>(spk, pot, win);
}

// round 17
// speedup vs baseline: 1.1551x; 1.1551x over previous
#include <cuda_runtime.h>
#include <cuda_fp16.h>
#include <stdint.h>

#define T_STEPS 15
#define C_IN    6
#define HW      256
#define NPIX    65536
#define C_OUT   64
#define THRESH  15.0f
#define NELEM   62914560
#define QTOT    160              // 150 real taps + 10 zero pads, q=(ky*5+kx)*6+i
#define NKB     64               // kwta blocks
#define BSTRIDE 44               // smem column stride in uint4 (bank-conflict-free)
#define MMAB    296              // persistent mma blocks (148 SM x 2)

__device__ __align__(16) uint4   g_wB[64 * 40];      // packed B frags [c][ch][b]
__device__ __align__(16) float   g_wqc[QTOT * 64];   // exact fp32 [q][c]
__device__ __align__(16) uint4   g_ftq[10 * NPIX];   // tf bytes, q-ordered
__device__ int                   g_winfo[NPIX];      // -1 or wc|(count<<8)
__device__ unsigned char         g_wc[NPIX];         // 255 none, 254 flagged
__device__ float                 g_firstpot[NPIX];
__device__ float                 g_winval[NPIX * 16];
__device__ float                 g_gband;
__device__ int                   g_vmax;
__device__ int                   g_nflag;
__device__ int                   g_flag[NPIX];
__device__ unsigned long long    g_part[NKB];
__device__ int                   g_banc[5];
__device__ int                   g_banp[5];
__device__ volatile int          g_barcnt;

// weight in q-order (q = (ky*5+kx)*6 + i); 0 for pad taps
__device__ __forceinline__ float wq(const float* wg, int c, int q)
{
    if (q >= 150) return 0.f;
    const int i = q % 6, r = q / 6, kx = r % 5, ky = r / 5;
    return wg[c * 150 + i * 25 + ky * 5 + kx];
}
__device__ __forceinline__ unsigned packh(float a, float b)
{
    const __half2 h = __halves2half2(__float2half_rn(a), __float2half_rn(b));
    return *(const unsigned*)&h;
}

// ---------------- K0: fused weight prep (blocks 0..51) + ftq (52..307) ------
__global__ __launch_bounds__(256) void prep_ftq_kernel(const float* __restrict__ in,
                                                       const float* __restrict__ wg)
{
    __shared__ unsigned char sft[C_IN * 20 * 20];
    const int tid = threadIdx.x;

    if (blockIdx.x < 52) {
        if (blockIdx.x == 51) {                  // control block
            __shared__ float sb[64];
            if (tid == 0) { g_nflag = 0; g_vmax = 0; *(int*)&g_barcnt = 0; }
            if (tid < 64) {
                float s = 0.f;
                for (int j = 0; j < 150; j++) {
                    const float w = wg[tid * 150 + j];
                    const float h1 = __half2float(__float2half_rn(w));
                    const float h2 = __half2float(__float2half_rn(w - h1));
                    s += fabsf(w - h1 - h2);     // exact residual magnitude
                }
                sb[tid] = s;
            }
            __syncthreads();
            if (tid < 32) sb[tid] = fmaxf(sb[tid], sb[tid + 32]);
            __syncwarp();
            if (tid < 16) sb[tid] = fmaxf(sb[tid], sb[tid + 16]);
            __syncwarp();
            if (tid < 8)  sb[tid] = fmaxf(sb[tid], sb[tid + 8]);
            __syncwarp();
            if (tid < 4)  sb[tid] = fmaxf(sb[tid], sb[tid + 4]);
            __syncwarp();
            // ref-chain drift 1.3e-3 + fused-accumulator rounding + key-mask + slack
            if (tid == 0) g_gband = fmaxf(fmaxf(sb[0], sb[1]), fmaxf(sb[2], sb[3])) + 1.7e-3f;
            return;
        }
        const int k = blockIdx.x * 256 + tid;
        if (k < 2560) {                          // packed B fragment records
            const int c = k / 40, r = k % 40, ch = r / 4, b = r % 4;
            const int q0 = ch * 16 + b * 2;
            float w0 = wq(wg, c, q0),     w1 = wq(wg, c, q0 + 1);
            float w8 = wq(wg, c, q0 + 8), w9 = wq(wg, c, q0 + 9);
            const float a0 = __half2float(__float2half_rn(w0));
            const float a1 = __half2float(__float2half_rn(w1));
            const float a8 = __half2float(__float2half_rn(w8));
            const float a9 = __half2float(__float2half_rn(w9));
            uint4 W;
            W.x = packh(w0, w1);                 // h1 @ k0,k0+1
            W.y = packh(w8, w9);                 // h1 @ k0+8,k0+9
            W.z = packh(w0 - a0, w1 - a1);       // h2 @ k0,k0+1
            W.w = packh(w8 - a8, w9 - a9);       // h2 @ k0+8,k0+9
            g_wB[k] = W;
        } else if (k < 2560 + QTOT * 64) {       // exact fp32 [q][c]
            const int idx = k - 2560;
            const int q = idx >> 6, c = idx & 63;
            g_wqc[q * 64 + c] = wq(wg, c, q);
        }
        return;
    }

    // ---- ftq part: fused first-spike-time + q-ordered byte stream ----
    const int fb = blockIdx.x - 52;              // 0..255
    const int x0 = (fb & 15) * 16, y0 = (fb >> 4) * 16;
    for (int k = tid; k < C_IN * 400; k += 256) {
        const int i = k / 400, rr = k % 400, yy = rr / 20, xx = rr % 20;
        const int gy = y0 + yy - 2, gx = x0 + xx - 2;
        unsigned char tf = 15;
        if (gy >= 0 && gy < HW && gx >= 0 && gx < HW) {
            const size_t base = (size_t)i * NPIX + gy * HW + gx;
#pragma unroll
            for (int t = T_STEPS - 1; t >= 0; t--)
                if (in[(size_t)t * C_IN * NPIX + base] > 0.f) tf = (unsigned char)t;
        }
        sft[k] = tf;
    }
    __syncthreads();
    const int px = tid & 15, py = tid >> 4;
    const int pix = (y0 + py) * HW + x0 + px;
#pragma unroll
    for (int ch = 0; ch < 10; ch++) {
        unsigned r[4] = {0u, 0u, 0u, 0u};
#pragma unroll
        for (int b = 0; b < 16; b++) {
            const int q = ch * 16 + b;
            unsigned v = 15u;
            if (q < 150) {
                const int ky = q / 30, kx = (q / 6) % 5, i = q % 6;
                v = sft[(i * 20 + py + ky) * 20 + px + kx];
            }
            r[b >> 2] |= v << ((b & 3) * 8);
        }
        g_ftq[ch * NPIX + pix] = make_uint4(r[0], r[1], r[2], r[3]);
    }
}

#define MMAH(d0,d1,d2,d3,a0,a1,a2,a3,b0,b1) \
    asm("mma.sync.aligned.m16n8k16.row.col.f32.f16.f16.f32 " \
        "{%0,%1,%2,%3},{%4,%5,%6,%7},{%8,%9},{%0,%1,%2,%3};" \
        : "+f"(d0),"+f"(d1),"+f"(d2),"+f"(d3) \
        : "r"(a0),"r"(a1),"r"(a2),"r"(a3),"r"(b0),"r"(b1))

// float top-2 (keys are non-negative): 3 FMNMX, fma-pipe eligible
#define TUPDF(m1,m2,kf) { (m2) = fmaxf((m2), fminf((m1), (kf))); (m1) = fmaxf((m1), (kf)); }

// per-pixel epilogue (identical decision bits to R11..R15)
__device__ __forceinline__ void mma_epilogue(
    int pix, int warp, int lane, int kq, int t1, float gb,
    float m1a, float m2a, float m1b, float m2b,
    unsigned (*su1)[16], unsigned (*su2)[16])
{
#pragma unroll
    for (int off = 1; off <= 2; off <<= 1) {
        float o1 = __shfl_xor_sync(0xffffffffu, m1a, off);
        float o2 = __shfl_xor_sync(0xffffffffu, m2a, off);
        m2a = fmaxf(m2a, o2); m2a = fmaxf(m2a, fminf(m1a, o1)); m1a = fmaxf(m1a, o1);
        o1 = __shfl_xor_sync(0xffffffffu, m1b, off);
        o2 = __shfl_xor_sync(0xffffffffu, m2b, off);
        m2b = fmaxf(m2b, o2); m2b = fmaxf(m2b, fminf(m1b, o1)); m1b = fmaxf(m1b, o1);
    }
    if (kq == 0) {
        su1[warp][t1] = __float_as_uint(m1a); su2[warp][t1] = __float_as_uint(m2a);
        if (t1 + 8 < 15) { su1[warp][t1 + 8] = __float_as_uint(m1b); su2[warp][t1 + 8] = __float_as_uint(m2b); }
    }
    __syncwarp();
    if (lane == 0) {
        bool flag = false;
        int te = 15;
#pragma unroll
        for (int t = 0; t < 15; t++) {
            const float m = __uint_as_float(su1[warp][t] & 0xFFFFFFC0u);
            if (fabsf(m - THRESH) < gb) flag = true;
            if (te == 15 && m >= THRESH) te = t;
        }
        if (te < 15) {
            const float v1 = __uint_as_float(su1[warp][te] & 0xFFFFFFC0u);
            const float v2 = __uint_as_float(su2[warp][te] & 0xFFFFFFC0u);
            if (v1 - v2 < 2.f * gb) flag = true;
        }
        if (flag) {
            const int s = atomicAdd(&g_nflag, 1);
            g_flag[s] = pix;
            g_wc[pix] = 254;
        } else if (te < 15) {
            const int cw = 63 - (int)(su1[warp][te] & 63u);
            g_wc[pix]    = (unsigned char)cw;
            g_winfo[pix] = cw | ((15 - te) << 8);
        } else {
            g_wc[pix] = 255; g_winfo[pix] = -1; g_firstpot[pix] = 0.f;
        }
    }
    __syncwarp();
}

// ---------------- K1: persistent MMA decision conv (pixel-pair B reuse) -----
__global__ __launch_bounds__(256, 2) void mma_kernel()
{
    __shared__ __align__(16) uint4 swB[64 * BSTRIDE];   // 45056 B
    __shared__ unsigned su1[8][16], su2[8][16];

    const int tid = threadIdx.x;
    for (int k = tid; k < 2560; k += 256) {
        const int c = k / 40, r = k % 40;
        swB[c * BSTRIDE + r] = g_wB[k];
    }
    __syncthreads();

    const int lane = tid & 31, warp = tid >> 5;
    const int t1 = lane >> 2;
    const int k0 = (lane & 3) * 2;
    const int kq = lane & 3;
    const int nB = lane >> 2;
    const unsigned tt1 = (unsigned)t1 * 0x01010101u;
    const unsigned tt2 = (unsigned)(t1 + 8) * 0x01010101u;
    const unsigned sel = ((k0 & 3) == 0) ? 0x1404u : 0x3424u;
    const float gb = g_gband;

    for (int grp = blockIdx.x; grp < NPIX / 64; grp += gridDim.x) {
        for (int pp = 0; pp < 4; pp++) {
            const int pix0 = grp * 64 + warp * 8 + pp * 2;
            const int pix1 = pix0 + 1;

            float acc0[8][4], acc1[8][4];
#pragma unroll
            for (int nt = 0; nt < 8; nt++)
#pragma unroll
                for (int j = 0; j < 4; j++) { acc0[nt][j] = 0.f; acc1[nt][j] = 0.f; }

#pragma unroll
            for (int ch = 0; ch < 10; ch++) {
                const uint4 T0 = __ldg(&g_ftq[ch * NPIX + pix0]);
                const uint4 T1 = __ldg(&g_ftq[ch * NPIX + pix1]);
                const unsigned wa0 = (k0 < 4) ? T0.x : T0.y;
                const unsigned wb0 = (k0 < 4) ? T0.z : T0.w;
                const unsigned wa1 = (k0 < 4) ? T1.x : T1.y;
                const unsigned wb1 = (k0 < 4) ? T1.z : T1.w;
                const unsigned A00 = __byte_perm(__vcmpleu4(wa0, tt1), 0, sel) & 0x3C003C00u;
                const unsigned A01 = __byte_perm(__vcmpleu4(wa0, tt2), 0, sel) & 0x3C003C00u;
                const unsigned A02 = __byte_perm(__vcmpleu4(wb0, tt1), 0, sel) & 0x3C003C00u;
                const unsigned A03 = __byte_perm(__vcmpleu4(wb0, tt2), 0, sel) & 0x3C003C00u;
                const unsigned A10 = __byte_perm(__vcmpleu4(wa1, tt1), 0, sel) & 0x3C003C00u;
                const unsigned A11 = __byte_perm(__vcmpleu4(wa1, tt2), 0, sel) & 0x3C003C00u;
                const unsigned A12 = __byte_perm(__vcmpleu4(wb1, tt1), 0, sel) & 0x3C003C00u;
                const unsigned A13 = __byte_perm(__vcmpleu4(wb1, tt2), 0, sel) & 0x3C003C00u;
#pragma unroll
                for (int nt = 0; nt < 8; nt++) {
                    const uint4 W = swB[(nt * 8 + nB) * BSTRIDE + ch * 4 + kq];
                    MMAH(acc0[nt][0], acc0[nt][1], acc0[nt][2], acc0[nt][3], A00, A01, A02, A03, W.x, W.y);
                    MMAH(acc0[nt][0], acc0[nt][1], acc0[nt][2], acc0[nt][3], A00, A01, A02, A03, W.z, W.w);
                    MMAH(acc1[nt][0], acc1[nt][1], acc1[nt][2], acc1[nt][3], A10, A11, A12, A13, W.x, W.y);
                    MMAH(acc1[nt][0], acc1[nt][1], acc1[nt][2], acc1[nt][3], A10, A11, A12, A13, W.z, W.w);
                }
            }

            float m1a0 = 0.f, m2a0 = 0.f, m1b0 = 0.f, m2b0 = 0.f;
            float m1a1 = 0.f, m2a1 = 0.f, m1b1 = 0.f, m2b1 = 0.f;
#pragma unroll
            for (int nt = 0; nt < 8; nt++) {
                const unsigned c0 = (unsigned)(nt * 8 + kq * 2);
                float k00 = __uint_as_float((__float_as_uint(acc0[nt][0]) & 0xFFFFFFC0u) | (63u - c0));
                float k01 = __uint_as_float((__float_as_uint(acc0[nt][1]) & 0xFFFFFFC0u) | (62u - c0));
                float k02 = __uint_as_float((__float_as_uint(acc0[nt][2]) & 0xFFFFFFC0u) | (63u - c0));
                float k03 = __uint_as_float((__float_as_uint(acc0[nt][3]) & 0xFFFFFFC0u) | (62u - c0));
                TUPDF(m1a0, m2a0, k00); TUPDF(m1a0, m2a0, k01);
                TUPDF(m1b0, m2b0, k02); TUPDF(m1b0, m2b0, k03);
                k00 = __uint_as_float((__float_as_uint(acc1[nt][0]) & 0xFFFFFFC0u) | (63u - c0));
                k01 = __uint_as_float((__float_as_uint(acc1[nt][1]) & 0xFFFFFFC0u) | (62u - c0));
                k02 = __uint_as_float((__float_as_uint(acc1[nt][2]) & 0xFFFFFFC0u) | (63u - c0));
                k03 = __uint_as_float((__float_as_uint(acc1[nt][3]) & 0xFFFFFFC0u) | (62u - c0));
                TUPDF(m1a1, m2a1, k00); TUPDF(m1a1, m2a1, k01);
                TUPDF(m1b1, m2b1, k02); TUPDF(m1b1, m2b1, k03);
            }

            mma_epilogue(pix0, warp, lane, kq, t1, gb, m1a0, m2a0, m1b0, m2b0, su1, su2);
            mma_epilogue(pix1, warp, lane, kq, t1, gb, m1a1, m2a1, m1b1, m2b1, su1, su2);
        }
    }
}

// ---------------- K2: fused series (blocks 0..511) + fallback (512..1023) ---
__global__ __launch_bounds__(256) void series_fb_kernel()
{
    __shared__ float swq[QTOT * 64];
    const int tid = threadIdx.x;
    const int lane = tid & 31, warp = tid >> 5;

    if (blockIdx.x < 512) {
        // ---- exact winner series, 2 threads per pixel (t-split) ----
        for (int k = tid; k < QTOT * 64; k += 256) swq[k] = g_wqc[k];
        __syncthreads();

        const int u = blockIdx.x * 256 + tid;   // 2*NPIX units
        const int pix = u >> 1, half = u & 1;
        const int wc = g_wc[pix];
        if (wc >= 64) return;
        const int t0 = half * 8;

        float acc[8];
#pragma unroll
        for (int j = 0; j < 8; j++) acc[j] = 0.f;

#pragma unroll
        for (int ch = 0; ch < 10; ch++) {
            const uint4 T = __ldg(&g_ftq[ch * NPIX + pix]);
            const unsigned W[4] = {T.x, T.y, T.z, T.w};
#pragma unroll
            for (int b = 0; b < 16; b++) {
                const int tf = (W[b >> 2] >> ((b & 3) * 8)) & 255;
                const float w = swq[(ch * 16 + b) * 64 + wc];
#pragma unroll
                for (int j = 0; j < 8; j++)
                    if (tf <= t0 + j) acc[j] += w;   // exact skip-zero chain, q order
            }
        }
        const int te = 15 - (g_winfo[pix] >> 8);
#pragma unroll
        for (int j = 0; j < 8; j++) {
            const int t = t0 + j;
            if (t < 15) {
                const float v = (acc[j] >= THRESH) ? acc[j] : 0.f;
                g_winval[pix * 16 + t] = v;
                if (t == te) {
                    g_firstpot[pix] = v;
                    atomicMax(&g_vmax, __float_as_int(v));
                }
            }
        }
        return;
    }

    // ---- exact fallback, warp per flagged pixel (2 channels per lane) ----
    const int gw = (blockIdx.x - 512) * 8 + warp;     // 0..4095
    const int nf = g_nflag;
    for (int f = gw; f < nf; f += 4096) {
        const int pix = g_flag[f];
        float acc0[15], acc1[15];
#pragma unroll
        for (int t = 0; t < 15; t++) { acc0[t] = 0.f; acc1[t] = 0.f; }
#pragma unroll
        for (int ch = 0; ch < 10; ch++) {
            const uint4 T = __ldg(&g_ftq[ch * NPIX + pix]);
            const unsigned W[4] = {T.x, T.y, T.z, T.w};
#pragma unroll
            for (int b = 0; b < 16; b++) {
                const int tf = (W[b >> 2] >> ((b & 3) * 8)) & 255;
                const float w0 = g_wqc[(ch * 16 + b) * 64 + lane];
                const float w1 = g_wqc[(ch * 16 + b) * 64 + lane + 32];
#pragma unroll
                for (int t = 0; t < 15; t++)
                    if (tf <= t) { acc0[t] += w0; acc1[t] += w1; }
            }
        }
        int te = 15;
        unsigned long long kte = 0ull;
#pragma unroll
        for (int t = 0; t < 15; t++) {
            const float v0 = (acc0[t] >= THRESH) ? acc0[t] : 0.f;
            const float v1 = (acc1[t] >= THRESH) ? acc1[t] : 0.f;
            unsigned long long k0 = ((unsigned long long)__float_as_uint(v0) << 8) | (unsigned)(63 - lane);
            unsigned long long k1 = ((unsigned long long)__float_as_uint(v1) << 8) | (unsigned)(31 - lane);
            unsigned long long k = (k0 > k1) ? k0 : k1;
#pragma unroll
            for (int off = 16; off; off >>= 1) {
                const unsigned long long o = __shfl_xor_sync(0xffffffffu, k, off);
                if (o > k) k = o;
            }
            if (te == 15 && (k >> 8) != 0ull) { te = t; kte = k; }
        }
        int cw = -1;
        if (te < 15) cw = 63 - (int)(kte & 0xff);
        if (lane == 0) {
            if (te < 15) {
                const float fp = __uint_as_float((unsigned)(kte >> 8));
                g_wc[pix] = (unsigned char)cw;
                g_winfo[pix] = cw | ((15 - te) << 8);
                g_firstpot[pix] = fp;
                atomicMax(&g_vmax, __float_as_int(fp));
            } else {
                g_wc[pix] = 255; g_winfo[pix] = -1; g_firstpot[pix] = 0.f;
            }
        }
        if (cw >= 0) {
            const int owner = cw & 31, half = cw >> 5;
            if (lane == owner) {
#pragma unroll
                for (int t = 0; t < 15; t++) {
                    const float a = half ? acc1[t] : acc0[t];
                    g_winval[pix * 16 + t] = (a >= THRESH) ? a : 0.f;
                }
            }
        }
        __syncwarp();
    }
}

// ---------------- K3: fused kwta (blocks 0..63) + emit (64..61503) ----------
__device__ __forceinline__ void grid_bar(int target)
{
    __syncthreads();
    if (threadIdx.x == 0) {
        __threadfence();
        atomicAdd((int*)&g_barcnt, 1);
        while (g_barcnt < target * NKB) { }
    }
    __syncthreads();
}

__global__ __launch_bounds__(256) void emit_kwta_kernel(float* __restrict__ spk,
                                                        float* __restrict__ pot,
                                                        float* __restrict__ owin)
{
    if (blockIdx.x < NKB) {
        // ---- k-WTA: 5 greedy rounds with software grid barrier ----
        __shared__ unsigned long long sk[256];
        const int tid = threadIdx.x, bid = blockIdx.x;
        const float v = __int_as_float(g_vmax) * (float)T_STEPS;
        volatile int* vbanc = g_banc;
        volatile int* vbanp = g_banp;

        for (int round = 0; round < 5; round++) {
            int bc[4], bh[4], bw[4];
#pragma unroll
            for (int b = 0; b < 4; b++) {
                if (b < round) { bc[b] = vbanc[b]; const int bp = vbanp[b]; bh[b] = bp >> 8; bw[b] = bp & 255; }
                else           { bc[b] = -1; bh[b] = -1000; bw[b] = -1000; }
            }
            unsigned long long best = 0;
            for (int p = bid * 256 + tid; p < NPIX; p += NKB * 256) {
                const int info = g_winfo[p];
                if (info < 0) continue;
                const int wc = info & 255;
                const int h = p >> 8, w = p & 255;
                bool ban = false;
#pragma unroll
                for (int b = 0; b < 4; b++) {
                    if (wc == bc[b]) ban = true;
                    if (h >= bh[b] - 3 && h <= bh[b] + 3 && w >= bw[b] - 3 && w <= bw[b] + 3) ban = true;
                }
                if (ban) continue;
                const float tot = (float)(info >> 8) * (g_firstpot[p] + v);
                const unsigned flat = ((unsigned)wc << 16) | (unsigned)p;
                const unsigned long long key =
                    ((unsigned long long)__float_as_uint(tot) << 32) | (unsigned)(~flat);
                if (key > best) best = key;
            }
            sk[tid] = best;
            __syncthreads();
            for (int s = 128; s >= 1; s >>= 1) {
                if (tid < s && sk[tid + s] > sk[tid]) sk[tid] = sk[tid + s];
                __syncthreads();
            }
            if (tid == 0)
                *(volatile unsigned long long*)&g_part[bid] = sk[0];

            grid_bar(2 * round + 1);

            if (bid == 0) {
                if (tid < NKB) sk[tid] = *(volatile unsigned long long*)&g_part[tid];
                else           sk[tid] = 0;
                __syncthreads();
                for (int s = 32; s >= 1; s >>= 1) {
                    if (tid < s && sk[tid + s] > sk[tid]) sk[tid] = sk[tid + s];
                    __syncthreads();
                }
                if (tid == 0) {
                    const unsigned long long k = sk[0];
                    if ((k >> 32) != 0ull) {
                        const unsigned flat = ~(unsigned)(k & 0xffffffffull);
                        const int c = (int)(flat >> 16), p = (int)(flat & 0xffff);
                        owin[round * 3 + 0] = (float)c;
                        owin[round * 3 + 1] = (float)(p >> 8);
                        owin[round * 3 + 2] = (float)(p & 255);
                        g_banc[round] = c; g_banp[round] = p;
                    } else {
                        owin[round * 3 + 0] = -1.f; owin[round * 3 + 1] = -1.f; owin[round * 3 + 2] = -1.f;
                        g_banc[round] = -1; g_banp[round] = (1000 << 8);
                    }
                    __threadfence();
                }
            }
            grid_bar(2 * round + 2);
        }
        return;
    }

    // ---- emit spk/pot ----
    const size_t u = (size_t)(blockIdx.x - NKB) * 256 + threadIdx.x;
    const int w4 = (int)(u & 63);
    size_t r = u >> 6;
    const int h = (int)(r & 255); r >>= 8;
    const int c = (int)(r & 63);
    const int t = (int)(r >> 6);
    const int pix = (h << 8) | (w4 << 2);
    const uchar4 wc = *reinterpret_cast<const uchar4*>(g_wc + pix);
    const size_t e = ((size_t)t * C_OUT + (size_t)c) * NPIX + (size_t)pix;
    float4 pv, sv;
    float v;
    v = (wc.x == c) ? g_winval[(size_t)(pix + 0) * 16 + t] : 0.f; pv.x = v; sv.x = (v > 0.f) ? 1.f : 0.f;
    v = (wc.y == c) ? g_winval[(size_t)(pix + 1) * 16 + t] : 0.f; pv.y = v; sv.y = (v > 0.f) ? 1.f : 0.f;
    v = (wc.z == c) ? g_winval[(size_t)(pix + 2) * 16 + t] : 0.f; pv.z = v; sv.z = (v > 0.f) ? 1.f : 0.f;
    v = (wc.w == c) ? g_winval[(size_t)(pix + 3) * 16 + t] : 0.f; pv.w = v; sv.w = (v > 0.f) ? 1.f : 0.f;
    *reinterpret_cast<float4*>(pot + e) = pv;
    *reinterpret_cast<float4*>(spk + e) = sv;
}

// ---------------------------------------------------------------------------
extern "C" void kernel_launch(void* const* d_in, const int* in_sizes, int n_in,
                              void* d_out, int out_size)
{
    (void)in_sizes; (void)n_in; (void)out_size;
    const float* in = (const float*)d_in[0];
    const float* w1 = (const float*)d_in[1];
    float* out = (float*)d_out;
    float* spk = out;
    float* pot = out + (size_t)NELEM;
    float* win = out + (size_t)2 * NELEM;

    prep_ftq_kernel<<<308, 256>>>(in, w1);
    mma_kernel<<<MMAB, 256>>>();
    series_fb_kernel<<<1024, 256>>>();
    emit_kwta_kernel<<<NKB + NELEM / 4 / 256, 256>>>(spk, pot, win);
}